// round 3
// baseline (speedup 1.0000x reference)
#include <cuda_runtime.h>
#include <math_constants.h>
#include <cstdint>

#define CCH 256
#define HW  65536     // 256*256 pixels
#define P_TILE 32

// ---------------- scratch (no allocations allowed) ----------------
__device__ float g_X[CCH * 256];       // X[c][n]  pooled support features
__device__ float g_protoT[CCH * 256];  // protoT[c][n]  normalized protos (transposed)
__device__ float g_mlo[CCH], g_mdi[CCH], g_mhi[CCH];
__device__ float g_sel[256];

// ---------------- reduction helpers ----------------
__device__ __forceinline__ float warp_sum(float v) {
#pragma unroll
    for (int o = 16; o; o >>= 1) v += __shfl_xor_sync(0xffffffffu, v, o);
    return v;
}
__device__ __forceinline__ float warp_max(float v) {
#pragma unroll
    for (int o = 16; o; o >>= 1) v = fmaxf(v, __shfl_xor_sync(0xffffffffu, v, o));
    return v;
}
__device__ __forceinline__ float blk_sum256(float v, float* s, int t) {
    v = warp_sum(v);
    __syncthreads();
    if ((t & 31) == 0) s[t >> 5] = v;
    __syncthreads();
    if (t < 32) {
        float x = (t < 8) ? s[t] : 0.f;
        x = warp_sum(x);
        if (t == 0) s[32] = x;
    }
    __syncthreads();
    float r = s[32];
    __syncthreads();
    return r;
}
__device__ __forceinline__ float blk_max256(float v, float* s, int t) {
    v = warp_max(v);
    __syncthreads();
    if ((t & 31) == 0) s[t >> 5] = v;
    __syncthreads();
    if (t < 32) {
        float x = (t < 8) ? s[t] : -CUDART_INF_F;
        x = warp_max(x);
        if (t == 0) s[32] = x;
    }
    __syncthreads();
    float r = s[32];
    __syncthreads();
    return r;
}

// ---------------- K1a: pool sup_x (16x16 avg) -> g_X[c][n] ----------------
// One block per channel c. Thread t owns image column w=t; accumulates the 16
// row-groups, then a shared transpose-reduce produces the 256 pooled outputs.
__global__ void pool_x_kernel(const float* __restrict__ sx) {
    int c = blockIdx.x, t = threadIdx.x;
    const float* base = sx + (size_t)c * HW + t;
    __shared__ float sm[16 * 256];
#pragma unroll
    for (int bh = 0; bh < 16; bh++) {
        float a = 0.f;
#pragma unroll
        for (int r = 0; r < 16; r++) a += base[(bh * 16 + r) * 256];
        sm[bh * 256 + t] = a;
    }
    __syncthreads();
    int bh = t >> 4, bw = t & 15;
    float s = 0.f;
#pragma unroll
    for (int k = 0; k < 16; k++) s += sm[bh * 256 + bw * 16 + k];
    g_X[c * 256 + t] = s * (1.f / 256.f);
}

// ---------------- K1b: pool sup_y -> sel[n] ----------------
__global__ void pool_y_kernel(const float* __restrict__ sy) {
    int t = threadIdx.x;
    const float* base = sy + t;
    __shared__ float sm[16 * 256];
#pragma unroll
    for (int bh = 0; bh < 16; bh++) {
        float a = 0.f;
#pragma unroll
        for (int r = 0; r < 16; r++) a += base[(bh * 16 + r) * 256];
        sm[bh * 256 + t] = a;
    }
    __syncthreads();
    int bh = t >> 4, bw = t & 15;
    float s = 0.f;
#pragma unroll
    for (int k = 0; k < 16; k++) s += sm[bh * 256 + bw * 16 + k];
    g_sel[t] = ((s * (1.f / 256.f)) > 0.5f) ? 1.f : 0.f;
}

// ---------------- K2: w1 row + softmax -> tridiagonal band of (A*cal) ----------------
// Block i computes row i of w1 = X X^T, its softmax max/sum, and writes the
// three band coefficients m_lo/m_di/m_hi (only band entries of soft are needed).
__global__ void band_kernel(const float* __restrict__ cal) {
    int i = blockIdx.x, t = threadIdx.x;
    __shared__ float xi[256];
    __shared__ float sred[40];
    xi[t] = g_X[i * 256 + t];
    __syncthreads();
    const float* xr = g_X + t * 256;
    float w = 0.f;
#pragma unroll 8
    for (int n = 0; n < 256; n++) w = fmaf(xi[n], xr[n], w);
    float mx = blk_max256(w, sred, t);
    float e = expf(w - mx);
    float S = blk_sum256(e, sred, t);
    if (t >= i - 1 && t <= i + 1) {
        float s = e / S;
        float m = cal[i * 256 + t] * (1.f + 0.2f * s);
        if (t == i - 1) g_mlo[i] = m;
        else if (t == i) g_mdi[i] = m;
        else g_mhi[i] = m;
    }
    if (t == 0) {
        if (i == 0)   g_mlo[0]   = 0.f;
        if (i == 255) g_mhi[255] = 0.f;
    }
}

// ---------------- K3: Xn = tridiag @ X, column-normalize -> protoT[c][n] ----------------
__global__ void proto_kernel() {
    int n = blockIdx.x, i = threadIdx.x;
    __shared__ float sred[40];
    float x0 = g_X[i * 256 + n];
    float xm = (i > 0)   ? g_X[(i - 1) * 256 + n] : 0.f;
    float xp = (i < 255) ? g_X[(i + 1) * 256 + n] : 0.f;
    float v = g_mlo[i] * xm + g_mdi[i] * x0 + g_mhi[i] * xp;
    float ss = blk_sum256(v * v, sred, i);
    float nrm = fmaxf(sqrtf(ss), 1e-4f);
    g_protoT[i * 256 + n] = v / nrm;
}

// ---------------- K4: fused dists + mask + softmax + pred + argmax ----------------
// Block owns 32 pixels; thread t owns proto n=t. Inner loop over c uses packed
// f32x2 FMAs (2x fp32 rate). buf is reused: q-tile during the GEMM, d-matrix after.
__global__ __launch_bounds__(256) void dist_kernel(const float* __restrict__ qry,
                                                   float* __restrict__ out) {
    int t = threadIdx.x;
    int p0 = blockIdx.x * P_TILE;
    __shared__ __align__(16) float buf[256 * P_TILE];
    __shared__ float partial[256];
    __shared__ float nrm[P_TILE];

    // load q tile (coalesced: warp covers one c-row of 32 pixels) + sumsq
    float ss = 0.f;
#pragma unroll
    for (int r = 0; r < 32; r++) {
        int idx = r * 256 + t;            // idx = c*32 + j
        float v = qry[(size_t)(idx >> 5) * HW + p0 + (idx & 31)];
        buf[idx] = v;
        ss += v * v;
    }
    partial[t] = ss;                      // thread t has fixed j = t&31
    __syncthreads();
    if (t < 32) {
        float s = 0.f;
#pragma unroll
        for (int k = 0; k < 8; k++) s += partial[t + 32 * k];
        nrm[t] = fmaxf(sqrtf(s), 1e-4f);
    }

    // main accumulation: acc[a] holds pixels (2a, 2a+1) packed as f32x2
    unsigned long long acc[16];
#pragma unroll
    for (int a = 0; a < 16; a++) acc[a] = 0ull;
    const float* pp = g_protoT + t;
#pragma unroll 4
    for (int c = 0; c < 256; c++) {
        float pt = __ldg(pp + (c << 8));
        unsigned int ptu = __float_as_uint(pt);
        unsigned long long pt2;
        asm("mov.b64 %0, {%1, %2};" : "=l"(pt2) : "r"(ptu), "r"(ptu));
        const ulonglong2* q2 = (const ulonglong2*)(buf + c * P_TILE);
#pragma unroll
        for (int u = 0; u < 8; u++) {
            ulonglong2 q = q2[u];
            asm("fma.rn.f32x2 %0, %1, %2, %0;" : "+l"(acc[2 * u])     : "l"(q.x), "l"(pt2));
            asm("fma.rn.f32x2 %0, %1, %2, %0;" : "+l"(acc[2 * u + 1]) : "l"(q.y), "l"(pt2));
        }
    }
    float selv = g_sel[t];
    __syncthreads();   // q reads done, nrm visible; buf now becomes d-matrix

    const float NEG = -1e9f;
#pragma unroll
    for (int a = 0; a < 16; a++) {
        unsigned int lo, hi;
        asm("mov.b64 {%0, %1}, %2;" : "=r"(lo), "=r"(hi) : "l"(acc[a]));
        int j0 = 2 * a, j1 = 2 * a + 1;
        float d0 = (selv > 0.f) ? __uint_as_float(lo) * (20.f / nrm[j0]) : NEG;
        float d1 = (selv > 0.f) ? __uint_as_float(hi) * (20.f / nrm[j1]) : NEG;
        buf[j0 * 256 + t] = d0;
        buf[j1 * 256 + t] = d1;
    }
    __syncthreads();

    // per-pixel softmax-weighted sum + first-tie argmax (jnp.argmax semantics)
    int w = t >> 5, lane = t & 31;
    for (int pix = w; pix < P_TILE; pix += 8) {
        const float* dp = buf + pix * 256;
        float bm = -CUDART_INF_F; int bi = 0;
#pragma unroll
        for (int k = 0; k < 8; k++) {
            int n = k * 32 + lane;
            float v = dp[n];
            if (v > bm) { bm = v; bi = n; }
        }
#pragma unroll
        for (int o = 16; o; o >>= 1) {
            float om = __shfl_xor_sync(0xffffffffu, bm, o);
            int   oi = __shfl_xor_sync(0xffffffffu, bi, o);
            if (om > bm || (om == bm && oi < bi)) { bm = om; bi = oi; }
        }
        float se = 0.f, sd = 0.f;
#pragma unroll
        for (int k = 0; k < 8; k++) {
            float v = dp[k * 32 + lane];
            float e = expf(v - bm);
            se += e; sd += e * v;
        }
        se = warp_sum(se); sd = warp_sum(sd);
        if (lane == 0) {
            out[p0 + pix]      = sd / se;       // pred_grid
            out[HW + p0 + pix] = (float)bi;     // debug_assign
        }
    }
}

// ---------------- launcher ----------------
extern "C" void kernel_launch(void* const* d_in, const int* in_sizes, int n_in,
                              void* d_out, int out_size) {
    const float* qry   = (const float*)d_in[0];   // (1,1,256,256,256)
    const float* sup_x = (const float*)d_in[1];   // (1,1,1,256,256,256)
    const float* sup_y = (const float*)d_in[2];   // (1,1,1,256,256)
    // d_in[3] = s_init_seed (unused by reference)
    const float* cal   = (const float*)d_in[4];   // (256,256)
    float* out = (float*)d_out;                   // 65536 pred + 65536 assign

    pool_x_kernel<<<256, 256>>>(sup_x);
    pool_y_kernel<<<1, 256>>>(sup_y);
    band_kernel<<<256, 256>>>(cal);
    proto_kernel<<<256, 256>>>();
    dist_kernel<<<HW / P_TILE, 256>>>(qry, out);
}

// round 4
// speedup vs baseline: 1.2696x; 1.2696x over previous
#include <cuda_runtime.h>
#include <math_constants.h>
#include <cstdint>

#define CCH 256
#define HW  65536     // 256*256 pixels
#define P_TILE 32

// ---------------- scratch (no allocations allowed) ----------------
__device__ float g_X[CCH * 256];       // X[c][n]  pooled support features
__device__ float g_protoC[CCH * 256];  // protoC[c][slot]  compacted normalized protos
__device__ float g_mlo[CCH], g_mdi[CCH], g_mhi[CCH];
__device__ float g_sel[256];
__device__ int   g_slot[256];          // n -> compact slot (valid if selected)
__device__ int   g_selidx[256];        // slot -> original n
__device__ int   g_S;                  // number of selected protos

// ---------------- reduction helpers ----------------
__device__ __forceinline__ float warp_sum(float v) {
#pragma unroll
    for (int o = 16; o; o >>= 1) v += __shfl_xor_sync(0xffffffffu, v, o);
    return v;
}
__device__ __forceinline__ float warp_max(float v) {
#pragma unroll
    for (int o = 16; o; o >>= 1) v = fmaxf(v, __shfl_xor_sync(0xffffffffu, v, o));
    return v;
}
__device__ __forceinline__ float blk_sum256(float v, float* s, int t) {
    v = warp_sum(v);
    __syncthreads();
    if ((t & 31) == 0) s[t >> 5] = v;
    __syncthreads();
    if (t < 32) {
        float x = (t < 8) ? s[t] : 0.f;
        x = warp_sum(x);
        if (t == 0) s[32] = x;
    }
    __syncthreads();
    float r = s[32];
    __syncthreads();
    return r;
}
__device__ __forceinline__ float blk_max256(float v, float* s, int t) {
    v = warp_max(v);
    __syncthreads();
    if ((t & 31) == 0) s[t >> 5] = v;
    __syncthreads();
    if (t < 32) {
        float x = (t < 8) ? s[t] : -CUDART_INF_F;
        x = warp_max(x);
        if (t == 0) s[32] = x;
    }
    __syncthreads();
    float r = s[32];
    __syncthreads();
    return r;
}

// exp(x) for x in [-90, 0] on the FMA pipe (no MUFU). deg-6 2^r Taylor,
// max rel err ~1e-7 on r in [-0.5, 0.5].
__device__ __forceinline__ float fast_exp_neg(float x) {
    float t = x * 1.44269504088896340736f;
    float n = rintf(t);
    float r = t - n;
    float p = 1.540353039338161e-4f;
    p = fmaf(p, r, 1.3333558146428443e-3f);
    p = fmaf(p, r, 9.618129107628477e-3f);
    p = fmaf(p, r, 5.550410866482158e-2f);
    p = fmaf(p, r, 2.402265069591007e-1f);
    p = fmaf(p, r, 6.931471805599453e-1f);
    p = fmaf(p, r, 1.0f);
    float s = __int_as_float(((int)n + 127) << 23);
    return p * s;
}

// ---------------- K1a: pool sup_x (16x16 avg) -> g_X[c][n] ----------------
__global__ void pool_x_kernel(const float* __restrict__ sx) {
    int c = blockIdx.x, t = threadIdx.x;
    const float* base = sx + (size_t)c * HW + t;
    __shared__ float sm[16 * 256];
#pragma unroll
    for (int bh = 0; bh < 16; bh++) {
        float a = 0.f;
#pragma unroll
        for (int r = 0; r < 16; r++) a += base[(bh * 16 + r) * 256];
        sm[bh * 256 + t] = a;
    }
    __syncthreads();
    int bh = t >> 4, bw = t & 15;
    float s = 0.f;
#pragma unroll
    for (int k = 0; k < 16; k++) s += sm[bh * 256 + bw * 16 + k];
    g_X[c * 256 + t] = s * (1.f / 256.f);
}

// ---------------- K1b: pool sup_y -> sel[n] ----------------
__global__ void pool_y_kernel(const float* __restrict__ sy) {
    int t = threadIdx.x;
    const float* base = sy + t;
    __shared__ float sm[16 * 256];
#pragma unroll
    for (int bh = 0; bh < 16; bh++) {
        float a = 0.f;
#pragma unroll
        for (int r = 0; r < 16; r++) a += base[(bh * 16 + r) * 256];
        sm[bh * 256 + t] = a;
    }
    __syncthreads();
    int bh = t >> 4, bw = t & 15;
    float s = 0.f;
#pragma unroll
    for (int k = 0; k < 16; k++) s += sm[bh * 256 + bw * 16 + k];
    g_sel[t] = ((s * (1.f / 256.f)) > 0.5f) ? 1.f : 0.f;
}

// ---------------- K1c: exclusive prefix scan of sel -> compaction maps ----------------
__global__ void selscan_kernel() {
    int t = threadIdx.x;
    __shared__ int ps[256];
    int s = (g_sel[t] > 0.f) ? 1 : 0;
    ps[t] = s;
    g_selidx[t] = 0;                 // default for unused slots
    __syncthreads();
    if (t == 0) {
        int acc = 0;
        for (int n = 0; n < 256; n++) { int v = ps[n]; ps[n] = acc; acc += v; }
        g_S = acc;
    }
    __syncthreads();
    g_slot[t] = ps[t];
    if (s) g_selidx[ps[t]] = t;      // slots are distinct; no race with default
}

// ---------------- K2: w1 row + softmax -> tridiagonal band of (A*cal) ----------------
__global__ void band_kernel(const float* __restrict__ cal) {
    int i = blockIdx.x, t = threadIdx.x;
    __shared__ float xi[256];
    __shared__ float sred[40];
    xi[t] = g_X[i * 256 + t];
    __syncthreads();
    const float* xr = g_X + t * 256;
    float w = 0.f;
#pragma unroll 8
    for (int n = 0; n < 256; n++) w = fmaf(xi[n], xr[n], w);
    float mx = blk_max256(w, sred, t);
    float e = expf(w - mx);
    float S = blk_sum256(e, sred, t);
    if (t >= i - 1 && t <= i + 1) {
        float s = e / S;
        float m = cal[i * 256 + t] * (1.f + 0.2f * s);
        if (t == i - 1) g_mlo[i] = m;
        else if (t == i) g_mdi[i] = m;
        else g_mhi[i] = m;
    }
    if (t == 0) {
        if (i == 0)   g_mlo[0]   = 0.f;
        if (i == 255) g_mhi[255] = 0.f;
    }
}

// ---------------- K3: tridiag apply + column-normalize -> compacted protoC ----------------
__global__ void proto_kernel() {
    int n = blockIdx.x, i = threadIdx.x;
    __shared__ float sred[40];
    float x0 = g_X[i * 256 + n];
    float xm = (i > 0)   ? g_X[(i - 1) * 256 + n] : 0.f;
    float xp = (i < 255) ? g_X[(i + 1) * 256 + n] : 0.f;
    float v = g_mlo[i] * xm + g_mdi[i] * x0 + g_mhi[i] * xp;
    float ss = blk_sum256(v * v, sred, i);
    float nrm = fmaxf(sqrtf(ss), 1e-4f);
    if (g_sel[n] > 0.f) g_protoC[i * 256 + g_slot[n]] = v / nrm;
}

// ---------------- K4: fused dists + softmax + pred + argmax (compacted) ----------------
// Block owns 32 pixels; thread t owns compacted proto slot t (t < S).
__global__ __launch_bounds__(256) void dist_kernel(const float* __restrict__ qry,
                                                   float* __restrict__ out) {
    int t = threadIdx.x;
    int p0 = blockIdx.x * P_TILE;
    __shared__ __align__(16) float buf[256 * P_TILE];
    __shared__ float partial[256];
    __shared__ float nrm[P_TILE];
    __shared__ int sidx[256];
    __shared__ int sS;

    if (t == 0) sS = g_S;
    sidx[t] = g_selidx[t];

    // load q tile (coalesced) + per-pixel sumsq
    float ss = 0.f;
#pragma unroll
    for (int r = 0; r < 32; r++) {
        int idx = r * 256 + t;            // idx = c*32 + j
        float v = qry[(size_t)(idx >> 5) * HW + p0 + (idx & 31)];
        buf[idx] = v;
        ss += v * v;
    }
    partial[t] = ss;
    __syncthreads();
    if (t < 32) {
        float s = 0.f;
#pragma unroll
        for (int k = 0; k < 8; k++) s += partial[t + 32 * k];
        nrm[t] = fmaxf(sqrtf(s), 1e-4f);
    }
    int S = sS;

    // main accumulation (only threads owning a selected proto do work)
    unsigned long long acc[16];
#pragma unroll
    for (int a = 0; a < 16; a++) acc[a] = 0ull;
    if (t < S) {
        const float* pp = g_protoC + t;
#pragma unroll 4
        for (int c = 0; c < 256; c++) {
            float pt = __ldg(pp + (c << 8));
            unsigned int ptu = __float_as_uint(pt);
            unsigned long long pt2;
            asm("mov.b64 %0, {%1, %2};" : "=l"(pt2) : "r"(ptu), "r"(ptu));
            const ulonglong2* q2 = (const ulonglong2*)(buf + c * P_TILE);
#pragma unroll
            for (int u = 0; u < 8; u++) {
                ulonglong2 q = q2[u];
                asm("fma.rn.f32x2 %0, %1, %2, %0;" : "+l"(acc[2 * u])     : "l"(q.x), "l"(pt2));
                asm("fma.rn.f32x2 %0, %1, %2, %0;" : "+l"(acc[2 * u + 1]) : "l"(q.y), "l"(pt2));
            }
        }
    }
    __syncthreads();   // q reads done, nrm visible; buf becomes d-matrix

    const float NEG = -1e9f;
#pragma unroll
    for (int a = 0; a < 16; a++) {
        unsigned int lo, hi;
        asm("mov.b64 {%0, %1}, %2;" : "=r"(lo), "=r"(hi) : "l"(acc[a]));
        int j0 = 2 * a, j1 = 2 * a + 1;
        float d0 = (t < S) ? __uint_as_float(lo) * (20.f / nrm[j0]) : NEG;
        float d1 = (t < S) ? __uint_as_float(hi) * (20.f / nrm[j1]) : NEG;
        buf[j0 * 256 + t] = d0;
        buf[j1 * 256 + t] = d1;
    }
    __syncthreads();

    // per-pixel softmax-weighted sum + first-tie argmax over selected slots only
    int w = t >> 5, lane = t & 31;
    int kmax = (S + 31) >> 5;
    for (int pix = w; pix < P_TILE; pix += 8) {
        if (S == 0) {   // all masked: softmax uniform over equal -1e9 values
            if (lane == 0) { out[p0 + pix] = NEG; out[HW + p0 + pix] = 0.f; }
            continue;
        }
        const float* dp = buf + pix * 256;
        float bm = -CUDART_INF_F; int bi = 0;
        for (int k = 0; k < kmax; k++) {
            int n = k * 32 + lane;
            float v = (n < S) ? dp[n] : -CUDART_INF_F;
            if (v > bm) { bm = v; bi = n; }
        }
#pragma unroll
        for (int o = 16; o; o >>= 1) {
            float om = __shfl_xor_sync(0xffffffffu, bm, o);
            int   oi = __shfl_xor_sync(0xffffffffu, bi, o);
            if (om > bm || (om == bm && oi < bi)) { bm = om; bi = oi; }
        }
        float se = 0.f, sd = 0.f;
        for (int k = 0; k < kmax; k++) {
            int n = k * 32 + lane;
            if (n < S) {
                float v = dp[n];
                float e = fast_exp_neg(v - bm);
                se += e; sd += e * v;
            }
        }
        se = warp_sum(se); sd = warp_sum(sd);
        if (lane == 0) {
            out[p0 + pix]      = sd / se;              // pred_grid
            out[HW + p0 + pix] = (float)sidx[bi];      // debug_assign (original index)
        }
    }
}

// ---------------- launcher ----------------
extern "C" void kernel_launch(void* const* d_in, const int* in_sizes, int n_in,
                              void* d_out, int out_size) {
    const float* qry   = (const float*)d_in[0];   // (1,1,256,256,256)
    const float* sup_x = (const float*)d_in[1];   // (1,1,1,256,256,256)
    const float* sup_y = (const float*)d_in[2];   // (1,1,1,256,256)
    // d_in[3] = s_init_seed (unused by reference)
    const float* cal   = (const float*)d_in[4];   // (256,256)
    float* out = (float*)d_out;                   // 65536 pred + 65536 assign

    pool_x_kernel<<<256, 256>>>(sup_x);
    pool_y_kernel<<<1, 256>>>(sup_y);
    selscan_kernel<<<1, 256>>>();
    band_kernel<<<256, 256>>>(cal);
    proto_kernel<<<256, 256>>>();
    dist_kernel<<<HW / P_TILE, 256>>>(qry, out);
}

// round 5
// speedup vs baseline: 1.6954x; 1.3353x over previous
#include <cuda_runtime.h>
#include <math_constants.h>
#include <cstdint>

#define CCH 256
#define HW  65536     // 256*256 pixels
#define P_TILE 32

// ---------------- scratch (no allocations allowed) ----------------
__device__ float g_X[CCH * 256];       // X[c][n]  pooled support features
__device__ float g_protoC[CCH * 256];  // protoC[c][slot]  compacted normalized protos
__device__ float g_mlo[CCH], g_mdi[CCH], g_mhi[CCH];
__device__ float g_sel[256];
__device__ int   g_slot[256];          // n -> compact slot (valid if selected)
__device__ int   g_selidx[256];        // slot -> original n
__device__ int   g_S;                  // number of selected protos

// ---------------- reduction helpers ----------------
__device__ __forceinline__ float warp_sum(float v) {
#pragma unroll
    for (int o = 16; o; o >>= 1) v += __shfl_xor_sync(0xffffffffu, v, o);
    return v;
}
__device__ __forceinline__ float warp_max(float v) {
#pragma unroll
    for (int o = 16; o; o >>= 1) v = fmaxf(v, __shfl_xor_sync(0xffffffffu, v, o));
    return v;
}
__device__ __forceinline__ float blk_sum256(float v, float* s, int t) {
    v = warp_sum(v);
    __syncthreads();
    if ((t & 31) == 0) s[t >> 5] = v;
    __syncthreads();
    if (t < 32) {
        float x = (t < 8) ? s[t] : 0.f;
        x = warp_sum(x);
        if (t == 0) s[32] = x;
    }
    __syncthreads();
    float r = s[32];
    __syncthreads();
    return r;
}

// exp(x) for x <= 0 on the FMA pipe (no MUFU). deg-6 2^r Taylor.
__device__ __forceinline__ float fast_exp_neg(float x) {
    float t = x * 1.44269504088896340736f;
    float n = rintf(t);
    float r = t - n;
    float p = 1.540353039338161e-4f;
    p = fmaf(p, r, 1.3333558146428443e-3f);
    p = fmaf(p, r, 9.618129107628477e-3f);
    p = fmaf(p, r, 5.550410866482158e-2f);
    p = fmaf(p, r, 2.402265069591007e-1f);
    p = fmaf(p, r, 6.931471805599453e-1f);
    p = fmaf(p, r, 1.0f);
    float s = __int_as_float(((int)n + 127) << 23);
    return p * s;
}

// ---------------- K1a: pool sup_x (16x16 avg) -> g_X[c][n] ----------------
__global__ void pool_x_kernel(const float* __restrict__ sx) {
    int c = blockIdx.x, t = threadIdx.x;
    const float* base = sx + (size_t)c * HW + t;
    __shared__ float sm[16 * 256];
#pragma unroll
    for (int bh = 0; bh < 16; bh++) {
        float a = 0.f;
#pragma unroll
        for (int r = 0; r < 16; r++) a += base[(bh * 16 + r) * 256];
        sm[bh * 256 + t] = a;
    }
    __syncthreads();
    int bh = t >> 4, bw = t & 15;
    float s = 0.f;
#pragma unroll
    for (int k = 0; k < 16; k++) s += sm[bh * 256 + bw * 16 + k];
    g_X[c * 256 + t] = s * (1.f / 256.f);
}

// ---------------- K1b: pool sup_y -> sel[n] ----------------
__global__ void pool_y_kernel(const float* __restrict__ sy) {
    int t = threadIdx.x;
    const float* base = sy + t;
    __shared__ float sm[16 * 256];
#pragma unroll
    for (int bh = 0; bh < 16; bh++) {
        float a = 0.f;
#pragma unroll
        for (int r = 0; r < 16; r++) a += base[(bh * 16 + r) * 256];
        sm[bh * 256 + t] = a;
    }
    __syncthreads();
    int bh = t >> 4, bw = t & 15;
    float s = 0.f;
#pragma unroll
    for (int k = 0; k < 16; k++) s += sm[bh * 256 + bw * 16 + k];
    g_sel[t] = ((s * (1.f / 256.f)) > 0.5f) ? 1.f : 0.f;
}

// ---------------- K1c: exclusive prefix scan of sel -> compaction maps ----------------
__global__ void selscan_kernel() {
    int t = threadIdx.x;
    __shared__ int ps[256];
    int s = (g_sel[t] > 0.f) ? 1 : 0;
    ps[t] = s;
    g_selidx[t] = 0;
    __syncthreads();
    if (t == 0) {
        int acc = 0;
        for (int n = 0; n < 256; n++) { int v = ps[n]; ps[n] = acc; acc += v; }
        g_S = acc;
    }
    __syncthreads();
    g_slot[t] = ps[t];
    if (s) g_selidx[ps[t]] = t;
}

// ---------------- K2: w1 rows + softmax -> tridiagonal band of (A*cal) ----------------
// 64 blocks x 4 rows. All global loads coalesced via k-chunked shared tile of X;
// own row cached in registers; i-row values read as smem broadcasts.
#define BK_ROWS 4
__global__ __launch_bounds__(256) void band_kernel(const float* __restrict__ cal) {
    int t = threadIdx.x;
    int i0 = blockIdx.x * BK_ROWS;
    __shared__ float tile[256 * 33];          // 256 rows x 32 cols, stride 33 (conflict-free)
    __shared__ float wrow[BK_ROWS][256];
    float acc[BK_ROWS] = {0.f, 0.f, 0.f, 0.f};

    for (int k0 = 0; k0 < 256; k0 += 32) {
        __syncthreads();
#pragma unroll
        for (int it = 0; it < 32; it++) {
            int idx = t + it * 256;
            int r = idx >> 5, kk = idx & 31;
            tile[r * 33 + kk] = g_X[r * 256 + k0 + kk];   // warp = 128B contiguous
        }
        __syncthreads();
        float own[32];
#pragma unroll
        for (int kk = 0; kk < 32; kk++) own[kk] = tile[t * 33 + kk];
#pragma unroll
        for (int i = 0; i < BK_ROWS; i++) {
            const float* xi = &tile[(i0 + i) * 33];
            float a = acc[i];
#pragma unroll
            for (int kk = 0; kk < 32; kk++) a = fmaf(own[kk], xi[kk], a);
            acc[i] = a;
        }
    }
#pragma unroll
    for (int i = 0; i < BK_ROWS; i++) wrow[i][t] = acc[i];
    __syncthreads();

    int w = t >> 5, lane = t & 31;
    if (w < BK_ROWS) {
        int i = i0 + w;
        float mx = -CUDART_INF_F;
#pragma unroll
        for (int k = 0; k < 8; k++) mx = fmaxf(mx, wrow[w][k * 32 + lane]);
        mx = warp_max(mx);
        float s = 0.f;
#pragma unroll
        for (int k = 0; k < 8; k++) s += expf(wrow[w][k * 32 + lane] - mx);
        s = warp_sum(s);
        if (lane == 0) {
            float inv = 1.f / s;
            if (i > 0) {
                float e = expf(wrow[w][i - 1] - mx) * inv;
                g_mlo[i] = cal[i * 256 + (i - 1)] * (1.f + 0.2f * e);
            } else g_mlo[0] = 0.f;
            {
                float e = expf(wrow[w][i] - mx) * inv;
                g_mdi[i] = cal[i * 256 + i] * (1.f + 0.2f * e);
            }
            if (i < 255) {
                float e = expf(wrow[w][i + 1] - mx) * inv;
                g_mhi[i] = cal[i * 256 + (i + 1)] * (1.f + 0.2f * e);
            } else g_mhi[255] = 0.f;
        }
    }
}

// ---------------- K3: tridiag apply + column-normalize -> compacted protoC ----------------
__global__ void proto_kernel() {
    int n = blockIdx.x, i = threadIdx.x;
    __shared__ float sred[40];
    float x0 = g_X[i * 256 + n];
    float xm = (i > 0)   ? g_X[(i - 1) * 256 + n] : 0.f;
    float xp = (i < 255) ? g_X[(i + 1) * 256 + n] : 0.f;
    float v = g_mlo[i] * xm + g_mdi[i] * x0 + g_mhi[i] * xp;
    float ss = blk_sum256(v * v, sred, i);
    float nrm = fmaxf(sqrtf(ss), 1e-4f);
    if (g_sel[n] > 0.f) g_protoC[i * 256 + g_slot[n]] = v / nrm;
}

// ---------------- K4: fused dists + softmax + pred + argmax ----------------
// Block owns 32 pixels. When 2S <= 256, threads split the channel range two-way
// (group 0: c 0..127, group 1: c 128..255) and combine partials through smem,
// doubling FMA-lane utilization for S ~= 128.
__global__ __launch_bounds__(256) void dist_kernel(const float* __restrict__ qry,
                                                   float* __restrict__ out) {
    int t = threadIdx.x;
    int p0 = blockIdx.x * P_TILE;
    __shared__ __align__(16) float buf[256 * P_TILE];
    __shared__ float partial[256];
    __shared__ float nrm[P_TILE];
    __shared__ int sidx[256];
    __shared__ int sS;

    if (t == 0) sS = g_S;
    sidx[t] = g_selidx[t];

    // load q tile (coalesced) + per-pixel sumsq
    float ss = 0.f;
#pragma unroll
    for (int r = 0; r < 32; r++) {
        int idx = r * 256 + t;            // idx = c*32 + j
        float v = qry[(size_t)(idx >> 5) * HW + p0 + (idx & 31)];
        buf[idx] = v;
        ss += v * v;
    }
    partial[t] = ss;
    __syncthreads();
    if (t < 32) {
        float s = 0.f;
#pragma unroll
        for (int k = 0; k < 8; k++) s += partial[t + 32 * k];
        nrm[t] = fmaxf(sqrtf(s), 1e-4f);
    }
    int S = sS;
    bool split = (S > 0) && (2 * S <= 256);
    int group = -1, slot = t;
    if (split) {
        if (t < S)          { group = 0; slot = t; }
        else if (t < 2 * S) { group = 1; slot = t - S; }
    } else if (t < S) {
        group = 0;
    }
    int cbeg = (group == 1) ? 128 : 0;
    int cend = (split && group == 0) ? 128 : 256;

    unsigned long long acc[16];
#pragma unroll
    for (int a = 0; a < 16; a++) acc[a] = 0ull;
    if (group >= 0) {
        const float* pp = g_protoC + slot;
#pragma unroll 4
        for (int c = cbeg; c < cend; c++) {
            float pt = __ldg(pp + (c << 8));
            unsigned int ptu = __float_as_uint(pt);
            unsigned long long pt2;
            asm("mov.b64 %0, {%1, %2};" : "=l"(pt2) : "r"(ptu), "r"(ptu));
            const ulonglong2* q2 = (const ulonglong2*)(buf + c * P_TILE);
#pragma unroll
            for (int u = 0; u < 8; u++) {
                ulonglong2 q = q2[u];
                asm("fma.rn.f32x2 %0, %1, %2, %0;" : "+l"(acc[2 * u])     : "l"(q.x), "l"(pt2));
                asm("fma.rn.f32x2 %0, %1, %2, %0;" : "+l"(acc[2 * u + 1]) : "l"(q.y), "l"(pt2));
            }
        }
    }
    __syncthreads();   // q reads done everywhere; buf reusable

    if (split) {
        unsigned long long* pb = (unsigned long long*)buf;   // 16KB partial region
        if (group == 1) {
#pragma unroll
            for (int a = 0; a < 16; a++) pb[a * 128 + slot] = acc[a];
        }
        __syncthreads();
        if (group == 0) {
#pragma unroll
            for (int a = 0; a < 16; a++) {
                unsigned long long o = pb[a * 128 + slot];
                asm("add.rn.f32x2 %0, %0, %1;" : "+l"(acc[a]) : "l"(o));
            }
        }
        __syncthreads();
    }

    const float NEG = -1e9f;
#pragma unroll
    for (int a = 0; a < 16; a++) {
        unsigned int lo, hi;
        asm("mov.b64 {%0, %1}, %2;" : "=r"(lo), "=r"(hi) : "l"(acc[a]));
        int j0 = 2 * a, j1 = 2 * a + 1;
        float d0 = (t < S) ? __uint_as_float(lo) * (20.f / nrm[j0]) : NEG;
        float d1 = (t < S) ? __uint_as_float(hi) * (20.f / nrm[j1]) : NEG;
        buf[j0 * 256 + t] = d0;
        buf[j1 * 256 + t] = d1;
    }
    __syncthreads();

    // per-pixel softmax-weighted sum + first-tie argmax over selected slots only
    int w = t >> 5, lane = t & 31;
    int kmax = (S + 31) >> 5;
    for (int pix = w; pix < P_TILE; pix += 8) {
        if (S == 0) {
            if (lane == 0) { out[p0 + pix] = NEG; out[HW + p0 + pix] = 0.f; }
            continue;
        }
        const float* dp = buf + pix * 256;
        float bm = -CUDART_INF_F; int bi = 0;
        for (int k = 0; k < kmax; k++) {
            int n = k * 32 + lane;
            float v = (n < S) ? dp[n] : -CUDART_INF_F;
            if (v > bm) { bm = v; bi = n; }
        }
#pragma unroll
        for (int o = 16; o; o >>= 1) {
            float om = __shfl_xor_sync(0xffffffffu, bm, o);
            int   oi = __shfl_xor_sync(0xffffffffu, bi, o);
            if (om > bm || (om == bm && oi < bi)) { bm = om; bi = oi; }
        }
        float se = 0.f, sd = 0.f;
        for (int k = 0; k < kmax; k++) {
            int n = k * 32 + lane;
            if (n < S) {
                float v = dp[n];
                float e = fast_exp_neg(v - bm);
                se += e; sd += e * v;
            }
        }
        se = warp_sum(se); sd = warp_sum(sd);
        if (lane == 0) {
            out[p0 + pix]      = sd / se;              // pred_grid
            out[HW + p0 + pix] = (float)sidx[bi];      // debug_assign (original index)
        }
    }
}

// ---------------- launcher ----------------
extern "C" void kernel_launch(void* const* d_in, const int* in_sizes, int n_in,
                              void* d_out, int out_size) {
    const float* qry   = (const float*)d_in[0];   // (1,1,256,256,256)
    const float* sup_x = (const float*)d_in[1];   // (1,1,1,256,256,256)
    const float* sup_y = (const float*)d_in[2];   // (1,1,1,256,256)
    // d_in[3] = s_init_seed (unused by reference)
    const float* cal   = (const float*)d_in[4];   // (256,256)
    float* out = (float*)d_out;                   // 65536 pred + 65536 assign

    pool_x_kernel<<<256, 256>>>(sup_x);
    pool_y_kernel<<<1, 256>>>(sup_y);
    selscan_kernel<<<1, 256>>>();
    band_kernel<<<64, 256>>>(cal);
    proto_kernel<<<256, 256>>>();
    dist_kernel<<<HW / P_TILE, 256>>>(qry, out);
}